// round 12
// baseline (speedup 1.0000x reference)
#include <cuda_runtime.h>

typedef unsigned long long u64;

// ---- packed f32x2 helpers (sm_100+ PTX) ----
__device__ __forceinline__ u64 pk2(float a, float b) {
    u64 r; asm("mov.b64 %0,{%1,%2};" : "=l"(r) : "f"(a), "f"(b)); return r;
}
__device__ __forceinline__ void up2(u64 v, float& a, float& b) {
    asm("mov.b64 {%0,%1},%2;" : "=f"(a), "=f"(b) : "l"(v));
}
__device__ __forceinline__ u64 f2fma(u64 a, u64 b, u64 c) {
    u64 d; asm("fma.rn.f32x2 %0,%1,%2,%3;" : "=l"(d) : "l"(a), "l"(b), "l"(c)); return d;
}
__device__ __forceinline__ u64 f2mul(u64 a, u64 b) {
    u64 d; asm("mul.rn.f32x2 %0,%1,%2;" : "=l"(d) : "l"(a), "l"(b)); return d;
}
__host__ __device__ constexpr u64 PKC(float f) {
    unsigned u = __builtin_bit_cast(unsigned, f);
    return ((u64)u << 32) | (u64)u;
}

// Tsit5 coefficients (fp32)
#define A21 0.161f
#define A31 (-0.008480655492356989f)
#define A32 0.335480655492357f
#define A41 2.8971530571054935f
#define A42 (-6.359448489975075f)
#define A43 4.3622954328695815f
#define A51 5.325864828439257f
#define A52 (-11.748883564062828f)
#define A53 7.4955393428898365f
#define A54 (-0.09249506636175525f)
#define A61 5.86145544294642f
#define A62 (-12.92096931784711f)
#define A63 8.159367898576159f
#define A64 (-0.071584973281401f)
#define A65 (-0.028269050394068383f)
#define B1 0.09646076681806523f
#define B2 0.01f
#define B3 0.4798896504144996f
#define B4 1.379008574103742f
#define B5 (-3.290069515436081f)
#define B6 2.324710524099774f
#define E1 (-0.001780011052225777f)
#define E2 (-0.0008164344596567469f)
#define E3 0.007880878010261995f
#define E4 (-0.1447110071732629f)
#define E5 0.5823571654525552f
#define E6 (-0.45808210592918697f)
#define E7 0.015151515151515152f

#define ATOL 1e-8f
#define RTOL 1e-4f
#define PRED_LEN 32
#define MAX_STEPS 12

// Integer-domain approximation of  FACC * ss^-0.1  (FACC = 0.9*0.25^-0.1):
//   bits(out) = C' - 0.1*bits(ss)
#define FAC_C 1172291263
#define FAC_TENTH 429496730u   // round(0.1 * 2^32)

// RHS producing packed k = (dS, dI). All negations folded into operand signs.
#define PRHS(Sv, Iv, kout)                                 \
    {                                                      \
        float _m   = nbN * (Sv);                           \
        float _infn = _m * (Iv);                           \
        kout = pk2(_infn, fmaf(ngm, (Iv), -_infn));        \
    }

__global__ void __launch_bounds__(32) sird_kernel(
    const float* __restrict__ x,          // [B,3] beta,gamma,mu
    const float* __restrict__ gp,         // [B,1]
    const float* __restrict__ population, // [B]
    float* __restrict__ out,              // [B,32,4]
    int B)
{
    int b = blockIdx.x * blockDim.x + threadIdx.x;
    if (b >= B) return;

    const float beta  = x[3 * b + 0];
    const float gamma = x[3 * b + 1];
    const float mu    = x[3 * b + 2];
    const float N     = population[b];
    const float bN    = beta / N;
    const float nbN   = -bN;
    const float gm    = gamma + mu;
    const float ngm   = -gm;

    float S = gp[b] - 100.0f;
    float I = 100.0f;
    float R = 0.0f;
    float D = 0.0f;

    float4* orow = reinterpret_cast<float4*>(out + (size_t)b * (PRED_LEN * 4));
    orow[0] = make_float4(S, I, R, D);

    float dt = 0.05f;
    const float tstep = 32.0f / 31.0f;

    // FSAL: k1 = RHS(S, I) carried across steps (autonomous RHS).
    u64 k1;
    PRHS(S, I, k1);

    for (int iv = 0; iv < PRED_LEN - 1; ++iv) {
        const float t1 = (float)(iv + 1) * tstep;
        float t = (float)iv * tstep;

        for (int s = 0; s < MAX_STEPS; ++s) {
            float h = fmaxf(fminf(dt, t1 - t), 1e-9f);
            u64 h2 = pk2(h, h);
            u64 y2 = pk2(S, I);

            float as, ai;
            const float I1 = I;

            u64 a2 = f2fma(h2, f2mul(PKC(A21), k1), y2);
            up2(a2, as, ai);
            const float I2 = ai;
            u64 k2; PRHS(as, ai, k2);

            a2 = f2fma(h2, f2fma(PKC(A32), k2, f2mul(PKC(A31), k1)), y2);
            up2(a2, as, ai);
            const float I3 = ai;
            u64 k3; PRHS(as, ai, k3);

            a2 = f2fma(h2, f2fma(PKC(A43), k3, f2fma(PKC(A42), k2, f2mul(PKC(A41), k1))), y2);
            up2(a2, as, ai);
            const float I4 = ai;
            u64 k4; PRHS(as, ai, k4);

            a2 = f2fma(h2, f2fma(PKC(A54), k4, f2fma(PKC(A53), k3, f2fma(PKC(A52), k2, f2mul(PKC(A51), k1)))), y2);
            up2(a2, as, ai);
            const float I5 = ai;
            u64 k5; PRHS(as, ai, k5);

            a2 = f2fma(h2, f2fma(PKC(A65), k5, f2fma(PKC(A64), k4, f2fma(PKC(A63), k3, f2fma(PKC(A62), k2, f2mul(PKC(A61), k1))))), y2);
            up2(a2, as, ai);
            const float I6 = ai;
            u64 k6; PRHS(as, ai, k6);

            u64 ny2 = f2fma(h2,
                f2fma(PKC(B6), k6, f2fma(PKC(B5), k5, f2fma(PKC(B4), k4,
                    f2fma(PKC(B3), k3, f2fma(PKC(B2), k2, f2mul(PKC(B1), k1)))))), y2);
            float nS, nI;
            up2(ny2, nS, nI);

            // R/D via factored I-stage sums: k_j^R = gamma*I_j, k_j^D = mu*I_j
            const float SB = fmaf(B6, I6, fmaf(B5, I5, fmaf(B4, I4, fmaf(B3, I3, fmaf(B2, I2, B1 * I1)))));
            const float hg = h * gamma;
            const float hm = h * mu;
            float nR = fmaf(hg, SB, R);
            float nD = fmaf(hm, SB, D);

            u64 k7; PRHS(nS, nI, k7);

            // packed error estimate for (S, I) — R/D components dropped from the
            // accept norm (they're non-binding; dropping non-negative terms only
            // loosens acceptance marginally, and S/I fully guard accuracy).
            u64 e2 = f2mul(h2,
                f2fma(PKC(E7), k7, f2fma(PKC(E6), k6, f2fma(PKC(E5), k5,
                    f2fma(PKC(E4), k4, f2fma(PKC(E3), k3, f2fma(PKC(E2), k2, f2mul(PKC(E1), k1))))))));
            float es, ei;
            up2(e2, es, ei);

            float ts_ = fmaf(RTOL, fmaxf(fabsf(S), fabsf(nS)), ATOL);
            float ti_ = fmaf(RTOL, fmaxf(fabsf(I), fabsf(nI)), ATOL);

            float rs = __fdividef(es, ts_);
            float ri = __fdividef(ei, ti_);
            // ss = 4*enorm^2 (with rr=rd=0); accept test ss <= 4 <=> enorm <= 1
            float ss = fmaf(rs, rs, ri * ri);

            // fac ~= clip(FACC * ss^-0.1, 0.2, 10) via integer log-domain trick.
            unsigned bs = (unsigned)__float_as_int(ss);
            int yb = FAC_C - (int)__umulhi(bs, FAC_TENTH);
            float fac = fminf(fmaxf(__int_as_float(yb), 0.2f), 10.0f);
            dt = h * fac;

            if (ss <= 4.0f) {
                t += h;
                S = nS; I = nI; R = nR; D = nD;
                k1 = k7;  // FSAL
            }
            if (t >= t1 - 1e-6f) break;
        }

        orow[iv + 1] = make_float4(S, I, R, D);
    }
}

extern "C" void kernel_launch(void* const* d_in, const int* in_sizes, int n_in,
                              void* d_out, int out_size)
{
    const float* x   = (const float*)d_in[0];
    const float* gp  = (const float*)d_in[1];
    const float* pop = (const float*)d_in[2];
    float* out = (float*)d_out;
    int B = in_sizes[2];  // population has B elements

    int threads = 32;
    int blocks = (B + threads - 1) / threads;
    sird_kernel<<<blocks, threads>>>(x, gp, pop, out, B);
}

// round 13
// speedup vs baseline: 1.2910x; 1.2910x over previous
#include <cuda_runtime.h>

typedef unsigned long long u64;

// ---- packed f32x2 helpers (sm_100+ PTX) ----
__device__ __forceinline__ u64 pk2(float a, float b) {
    u64 r; asm("mov.b64 %0,{%1,%2};" : "=l"(r) : "f"(a), "f"(b)); return r;
}
__device__ __forceinline__ void up2(u64 v, float& a, float& b) {
    asm("mov.b64 {%0,%1},%2;" : "=f"(a), "=f"(b) : "l"(v));
}
__device__ __forceinline__ u64 f2fma(u64 a, u64 b, u64 c) {
    u64 d; asm("fma.rn.f32x2 %0,%1,%2,%3;" : "=l"(d) : "l"(a), "l"(b), "l"(c)); return d;
}
__device__ __forceinline__ u64 f2mul(u64 a, u64 b) {
    u64 d; asm("mul.rn.f32x2 %0,%1,%2;" : "=l"(d) : "l"(a), "l"(b)); return d;
}
__host__ __device__ constexpr u64 PKC(float f) {
    unsigned u = __builtin_bit_cast(unsigned, f);
    return ((u64)u << 32) | (u64)u;
}

// Tsit5 coefficients (fp32)
#define A21 0.161f
#define A31 (-0.008480655492356989f)
#define A32 0.335480655492357f
#define A41 2.8971530571054935f
#define A42 (-6.359448489975075f)
#define A43 4.3622954328695815f
#define A51 5.325864828439257f
#define A52 (-11.748883564062828f)
#define A53 7.4955393428898365f
#define A54 (-0.09249506636175525f)
#define A61 5.86145544294642f
#define A62 (-12.92096931784711f)
#define A63 8.159367898576159f
#define A64 (-0.071584973281401f)
#define A65 (-0.028269050394068383f)
#define B1 0.09646076681806523f
#define B2 0.01f
#define B3 0.4798896504144996f
#define B4 1.379008574103742f
#define B5 (-3.290069515436081f)
#define B6 2.324710524099774f
#define E1 (-0.001780011052225777f)
#define E2 (-0.0008164344596567469f)
#define E3 0.007880878010261995f
#define E4 (-0.1447110071732629f)
#define E5 0.5823571654525552f
#define E6 (-0.45808210592918697f)
#define E7 0.015151515151515152f

#define ATOL 1e-8f
#define RTOL 1e-4f
#define PRED_LEN 32
#define MAX_STEPS 12

// Log-domain controller:
//   lrs = bits(|es|) - bits(ts)  ~  2^23 * log2(rs)
//   accept iff max(lrs,lri) <= 2^23   (max(rs,ri) <= 2  ~  ss <= 4)
//   bits(fac) = FAC1 - 0.2*lmax ;  FAC1 = bits(1.0f) + 2^23*log2(0.9*0.25^-0.1)
#define FAC1 1065755873
#define FAC_FIFTH 858993459   // round(0.2 * 2^32)
#define L_TWO (1 << 23)

// RHS producing packed k = (dS, dI). All negations folded into operand signs.
#define PRHS(Sv, Iv, kout)                                 \
    {                                                      \
        float _m   = nbN * (Sv);                           \
        float _infn = _m * (Iv);                           \
        kout = pk2(_infn, fmaf(ngm, (Iv), -_infn));        \
    }

__global__ void __launch_bounds__(32) sird_kernel(
    const float* __restrict__ x,          // [B,3] beta,gamma,mu
    const float* __restrict__ gp,         // [B,1]
    const float* __restrict__ population, // [B]
    float* __restrict__ out,              // [B,32,4]
    int B)
{
    int b = blockIdx.x * blockDim.x + threadIdx.x;
    if (b >= B) return;

    const float beta  = x[3 * b + 0];
    const float gamma = x[3 * b + 1];
    const float mu    = x[3 * b + 2];
    const float N     = population[b];
    const float bN    = beta / N;
    const float nbN   = -bN;
    const float gm    = gamma + mu;
    const float ngm   = -gm;

    float S = gp[b] - 100.0f;
    float I = 100.0f;
    float R = 0.0f;
    float D = 0.0f;

    float4* orow = reinterpret_cast<float4*>(out + (size_t)b * (PRED_LEN * 4));
    orow[0] = make_float4(S, I, R, D);

    float dt = 0.05f;
    const float tstep = 32.0f / 31.0f;

    // FSAL: k1 = RHS(S, I) carried across steps (autonomous RHS).
    u64 k1;
    PRHS(S, I, k1);

    for (int iv = 0; iv < PRED_LEN - 1; ++iv) {
        const float t1 = (float)(iv + 1) * tstep;
        float t = (float)iv * tstep;

        for (int s = 0; s < MAX_STEPS; ++s) {
            float h = fmaxf(fminf(dt, t1 - t), 1e-9f);
            u64 h2 = pk2(h, h);
            u64 y2 = pk2(S, I);

            float as, ai;
            const float I1 = I;

            u64 a2 = f2fma(h2, f2mul(PKC(A21), k1), y2);
            up2(a2, as, ai);
            const float I2 = ai;
            u64 k2; PRHS(as, ai, k2);

            a2 = f2fma(h2, f2fma(PKC(A32), k2, f2mul(PKC(A31), k1)), y2);
            up2(a2, as, ai);
            const float I3 = ai;
            u64 k3; PRHS(as, ai, k3);

            a2 = f2fma(h2, f2fma(PKC(A43), k3, f2fma(PKC(A42), k2, f2mul(PKC(A41), k1))), y2);
            up2(a2, as, ai);
            const float I4 = ai;
            u64 k4; PRHS(as, ai, k4);

            a2 = f2fma(h2, f2fma(PKC(A54), k4, f2fma(PKC(A53), k3, f2fma(PKC(A52), k2, f2mul(PKC(A51), k1)))), y2);
            up2(a2, as, ai);
            const float I5 = ai;
            u64 k5; PRHS(as, ai, k5);

            a2 = f2fma(h2, f2fma(PKC(A65), k5, f2fma(PKC(A64), k4, f2fma(PKC(A63), k3, f2fma(PKC(A62), k2, f2mul(PKC(A61), k1))))), y2);
            up2(a2, as, ai);
            const float I6 = ai;
            u64 k6; PRHS(as, ai, k6);

            u64 ny2 = f2fma(h2,
                f2fma(PKC(B6), k6, f2fma(PKC(B5), k5, f2fma(PKC(B4), k4,
                    f2fma(PKC(B3), k3, f2fma(PKC(B2), k2, f2mul(PKC(B1), k1)))))), y2);
            float nS, nI;
            up2(ny2, nS, nI);

            // R/D via factored I-stage sums: k_j^R = gamma*I_j, k_j^D = mu*I_j
            const float SB = fmaf(B6, I6, fmaf(B5, I5, fmaf(B4, I4, fmaf(B3, I3, fmaf(B2, I2, B1 * I1)))));
            const float hg = h * gamma;
            const float hm = h * mu;
            float nR = fmaf(hg, SB, R);
            float nD = fmaf(hm, SB, D);

            u64 k7; PRHS(nS, nI, k7);

            // packed error estimate for (S, I)
            u64 e2 = f2mul(h2,
                f2fma(PKC(E7), k7, f2fma(PKC(E6), k6, f2fma(PKC(E5), k5,
                    f2fma(PKC(E4), k4, f2fma(PKC(E3), k3, f2fma(PKC(E2), k2, f2mul(PKC(E1), k1))))))));
            float es, ei;
            up2(e2, es, ei);

            float ts_ = fmaf(RTOL, fmaxf(fabsf(S), fabsf(nS)), ATOL);
            float ti_ = fmaf(RTOL, fmaxf(fabsf(I), fabsf(nI)), ATOL);

            // ---- log-domain controller (divide-free) ----
            int lrs = (int)(__float_as_uint(es) & 0x7fffffffu) - (int)__float_as_uint(ts_);
            int lri = (int)(__float_as_uint(ei) & 0x7fffffffu) - (int)__float_as_uint(ti_);
            int lmax = max(lrs, lri);

            int facb = FAC1 - __mulhi(lmax, FAC_FIFTH);
            float fac = fminf(fmaxf(__int_as_float(facb), 0.2f), 10.0f);
            dt = h * fac;

            if (lmax <= L_TWO) {
                t += h;
                S = nS; I = nI; R = nR; D = nD;
                k1 = k7;  // FSAL
            }
            if (t >= t1 - 1e-6f) break;
        }

        orow[iv + 1] = make_float4(S, I, R, D);
    }
}

extern "C" void kernel_launch(void* const* d_in, const int* in_sizes, int n_in,
                              void* d_out, int out_size)
{
    const float* x   = (const float*)d_in[0];
    const float* gp  = (const float*)d_in[1];
    const float* pop = (const float*)d_in[2];
    float* out = (float*)d_out;
    int B = in_sizes[2];  // population has B elements

    int threads = 32;
    int blocks = (B + threads - 1) / threads;
    sird_kernel<<<blocks, threads>>>(x, gp, pop, out, B);
}